// round 4
// baseline (speedup 1.0000x reference)
#include <cuda_runtime.h>
#include <cuda_bf16.h>
#include <math.h>

#define NMAX 100000
#define HID 128
#define PROTO 64
#define BN_EPS 1e-5f

// ---------------- scratch (device globals: no allocation allowed) ----------------
__device__ float g_h1[NMAX * HID];
__device__ float g_h2[NMAX * HID];
__device__ float g_agg[NMAX * HID];
__device__ float g_p[NMAX * HID];
__device__ float g_p2[NMAX * HID];
__device__ float g_an[NMAX * PROTO];
__device__ float g_sim[NMAX];
__device__ int   g_cnt[NMAX];
__device__ float g_sum[4 * HID];
__device__ float g_sumsq[4 * HID];
__device__ float g_scale[HID];
__device__ float g_shift[HID];

// ---------------- f32x2 helpers (SASS FFMA2 via PTX) ----------------
__device__ __forceinline__ unsigned long long pk2(float lo, float hi) {
    unsigned long long r;
    asm("mov.b64 %0, {%1, %2};" : "=l"(r) : "f"(lo), "f"(hi));
    return r;
}
__device__ __forceinline__ void fma2(unsigned long long& d, unsigned long long a, unsigned long long b) {
    asm("fma.rn.f32x2 %0, %1, %2, %0;" : "+l"(d) : "l"(a), "l"(b));
}
__device__ __forceinline__ float2 upk2(unsigned long long v) {
    float2 r;
    asm("mov.b64 {%0, %1}, %2;" : "=f"(r.x), "=f"(r.y) : "l"(v));
    return r;
}

// ---------------- init ----------------
__global__ void init_kernel(int n) {
    int v = blockIdx.x * blockDim.x + threadIdx.x;
    if (v < n) { g_sim[v] = 1.0f; g_cnt[v] = 0; }  // self-loop sim == 1
    if (v < 4 * HID) { g_sum[v] = 0.f; g_sumsq[v] = 0.f; }
}

__global__ void count_kernel(const int* __restrict__ tgt, int E) {
    int e = blockIdx.x * blockDim.x + threadIdx.x;
    if (e < E) atomicAdd(&g_cnt[tgt[e]], 1);
}

// ---------------- gate branch ----------------
__global__ void normalize_alpha_kernel(const float* __restrict__ alpha, int n) {
    int v = blockIdx.x * blockDim.x + threadIdx.x;
    if (v >= n) return;
    const float4* a = (const float4*)(alpha + (size_t)v * PROTO);
    float4 vals[16];
    float ss = 0.f;
#pragma unroll
    for (int i = 0; i < 16; i++) {
        vals[i] = a[i];
        ss += vals[i].x * vals[i].x + vals[i].y * vals[i].y +
              vals[i].z * vals[i].z + vals[i].w * vals[i].w;
    }
    float inv = 1.0f / fmaxf(sqrtf(ss), 1e-12f);
    float4* o = (float4*)(g_an + (size_t)v * PROTO);
#pragma unroll
    for (int i = 0; i < 16; i++) {
        float4 t = vals[i];
        t.x *= inv; t.y *= inv; t.z *= inv; t.w *= inv;
        o[i] = t;
    }
}

// 8 lanes per edge; cooperative dot over 64 floats
__global__ void edge_sim_kernel(const int* __restrict__ src, const int* __restrict__ tgt, int E) {
    long long gt = (long long)blockIdx.x * blockDim.x + threadIdx.x;
    long long eL = gt >> 3;
    bool valid = eL < (long long)E;
    int e = valid ? (int)eL : 0;
    int sub = ((int)gt & 7) * 8;
    int s = __ldg(src + e), t = __ldg(tgt + e);
    const float4* as = (const float4*)(g_an + (size_t)s * PROTO + sub);
    const float4* at = (const float4*)(g_an + (size_t)t * PROTO + sub);
    float4 a0 = as[0], a1 = as[1], b0 = at[0], b1 = at[1];
    float d = a0.x * b0.x + a0.y * b0.y + a0.z * b0.z + a0.w * b0.w +
              a1.x * b1.x + a1.y * b1.y + a1.z * b1.z + a1.w * b1.w;
    if (!valid) d = 0.f;
    d += __shfl_down_sync(0xFFFFFFFFu, d, 4);
    d += __shfl_down_sync(0xFFFFFFFFu, d, 2);
    d += __shfl_down_sync(0xFFFFFFFFu, d, 1);
    if (valid && ((gt & 7) == 0)) atomicAdd(&g_sim[t], d);
}

__global__ void gate_final_kernel(const float* __restrict__ temp, float* __restrict__ out, int n) {
    int v = blockIdx.x * blockDim.x + threadIdx.x;
    if (v >= n) return;
    float tv = __ldg(temp);
    float m = g_sim[v] / (float)(g_cnt[v] + 1);   // +1: self loop; always >= 1
    out[v] = 1.0f / (1.0f + expf(-tv * m));
}

// ---------------- scatter (segment sum) ----------------
// 32 threads per edge, one float4 each, vector RED into agg[tgt]
__global__ void scatter_kernel(const float* __restrict__ h, const int* __restrict__ src,
                               const int* __restrict__ tgt, int E) {
    long long gt = (long long)blockIdx.x * blockDim.x + threadIdx.x;
    long long eL = gt >> 5;
    if (eL >= (long long)E) return;
    int e = (int)eL;
    int c = ((int)gt & 31) * 4;
    int s = __ldg(src + e), t = __ldg(tgt + e);
    float4 v = *(const float4*)(h + (size_t)s * HID + c);
    float* dst = &g_agg[(size_t)t * HID + c];
    asm volatile("red.global.add.v4.f32 [%0], {%1,%2,%3,%4};"
                 :: "l"(dst), "f"(v.x), "f"(v.y), "f"(v.z), "f"(v.w) : "memory");
}

// ---------------- GEMM (true FFMA2, zero packing movs in the hot loop) ----------------
// C[r][c] = bias[c] + sum_k A1[r][k]*W1[c][k] (+ A2[r][k]*W2[c][k])
// tile 64 rows x 128 cols, 256 threads.
// A stored TRANSPOSED in smem: asT[k][row]  -> LDS.128 broadcast = 2 packed row-pairs.
// W stored DUPLICATED in smem: wdup[k][2c] = (w,w) -> LDS.64 = ready f32x2 multiplier.
// lane owns cols {lane, lane+32, lane+64, lane+96} (bank-perfect LDS.64).
// STATS >= 0: fused BN column sum/sumsq into g_sum/g_sumsq[STATS*HID..]
template<int K, bool DUAL, bool MEAN1, int STATS>
__global__ __launch_bounds__(256) void gemm_kernel(
    const float* __restrict__ A1, const float* __restrict__ A2,
    const float* __restrict__ W1, const float* __restrict__ W2,
    const float* __restrict__ bias, float* __restrict__ C, int n)
{
    constexpr int BM = 64, KC = 16;
    __shared__ __align__(16) float asT1[KC][BM];
    __shared__ __align__(16) float asT2[KC][BM];
    __shared__ __align__(16) float wdup1[KC][2 * HID];
    __shared__ __align__(16) float wdup2[KC][2 * HID];
    __shared__ float rinv[BM];
    __shared__ float ssum[HID], ssq[HID];

    const int tid  = threadIdx.x;
    const int lane = tid & 31;
    const int w    = tid >> 5;
    const int row0 = blockIdx.x * BM;

    if (MEAN1 && tid < BM) {
        int r = row0 + tid;
        int cv = (r < n) ? g_cnt[r] : 1;
        rinv[tid] = 1.0f / (float)(cv > 0 ? cv : 1);
    }
    if (STATS >= 0 && tid < HID) { ssum[tid] = 0.f; ssq[tid] = 0.f; }

    unsigned long long acc[4][4];  // [row-pair][col j], rows = w*8+2rp, w*8+2rp+1
#pragma unroll
    for (int j = 0; j < 4; j++) {
        float b = bias[lane + 32 * j];
        unsigned long long bp = pk2(b, b);
#pragma unroll
        for (int rp = 0; rp < 4; rp++) acc[rp][j] = bp;
    }

    // A loader indices: one element set per thread
    const int ar  = tid >> 2;          // local row 0..63
    const int ac4 = (tid & 3) * 4;     // k offset 0,4,8,12
    // W loader indices
    const int wc  = tid & 127;         // col 0..127
    const int wkh = (tid >> 7) * 8;    // k half 0 or 8

    for (int k0 = 0; k0 < K; k0 += KC) {
        __syncthreads();
        // ---- A tile, transposed ----
        {
            int gr = row0 + ar;
            float4 v = make_float4(0.f, 0.f, 0.f, 0.f);
            if (gr < n) v = *(const float4*)(A1 + (size_t)gr * K + k0 + ac4);
            if (MEAN1) { float f = rinv[ar]; v.x *= f; v.y *= f; v.z *= f; v.w *= f; }
            asT1[ac4 + 0][ar] = v.x; asT1[ac4 + 1][ar] = v.y;
            asT1[ac4 + 2][ar] = v.z; asT1[ac4 + 3][ar] = v.w;
            if (DUAL) {
                float4 u = make_float4(0.f, 0.f, 0.f, 0.f);
                if (gr < n) u = *(const float4*)(A2 + (size_t)gr * K + k0 + ac4);
                asT2[ac4 + 0][ar] = u.x; asT2[ac4 + 1][ar] = u.y;
                asT2[ac4 + 2][ar] = u.z; asT2[ac4 + 3][ar] = u.w;
            }
        }
        // ---- W tile, duplicated ----
#pragma unroll
        for (int j = 0; j < 8; j += 4) {
            float4 v = *(const float4*)(W1 + (size_t)wc * K + k0 + wkh + j);
            *(float2*)&wdup1[wkh + j + 0][2 * wc] = make_float2(v.x, v.x);
            *(float2*)&wdup1[wkh + j + 1][2 * wc] = make_float2(v.y, v.y);
            *(float2*)&wdup1[wkh + j + 2][2 * wc] = make_float2(v.z, v.z);
            *(float2*)&wdup1[wkh + j + 3][2 * wc] = make_float2(v.w, v.w);
            if (DUAL) {
                float4 u = *(const float4*)(W2 + (size_t)wc * K + k0 + wkh + j);
                *(float2*)&wdup2[wkh + j + 0][2 * wc] = make_float2(u.x, u.x);
                *(float2*)&wdup2[wkh + j + 1][2 * wc] = make_float2(u.y, u.y);
                *(float2*)&wdup2[wkh + j + 2][2 * wc] = make_float2(u.z, u.z);
                *(float2*)&wdup2[wkh + j + 3][2 * wc] = make_float2(u.w, u.w);
            }
        }
        __syncthreads();
#pragma unroll
        for (int k = 0; k < KC; k++) {
            ulonglong2 aA = *(const ulonglong2*)&asT1[k][w * 8];       // (r0r1),(r2r3)
            ulonglong2 aB = *(const ulonglong2*)&asT1[k][w * 8 + 4];   // (r4r5),(r6r7)
            unsigned long long wv0 = *(const unsigned long long*)&wdup1[k][2 * lane];
            unsigned long long wv1 = *(const unsigned long long*)&wdup1[k][2 * (lane + 32)];
            unsigned long long wv2 = *(const unsigned long long*)&wdup1[k][2 * (lane + 64)];
            unsigned long long wv3 = *(const unsigned long long*)&wdup1[k][2 * (lane + 96)];
            fma2(acc[0][0], aA.x, wv0); fma2(acc[0][1], aA.x, wv1);
            fma2(acc[0][2], aA.x, wv2); fma2(acc[0][3], aA.x, wv3);
            fma2(acc[1][0], aA.y, wv0); fma2(acc[1][1], aA.y, wv1);
            fma2(acc[1][2], aA.y, wv2); fma2(acc[1][3], aA.y, wv3);
            fma2(acc[2][0], aB.x, wv0); fma2(acc[2][1], aB.x, wv1);
            fma2(acc[2][2], aB.x, wv2); fma2(acc[2][3], aB.x, wv3);
            fma2(acc[3][0], aB.y, wv0); fma2(acc[3][1], aB.y, wv1);
            fma2(acc[3][2], aB.y, wv2); fma2(acc[3][3], aB.y, wv3);
            if (DUAL) {
                ulonglong2 bA = *(const ulonglong2*)&asT2[k][w * 8];
                ulonglong2 bB = *(const ulonglong2*)&asT2[k][w * 8 + 4];
                unsigned long long uv0 = *(const unsigned long long*)&wdup2[k][2 * lane];
                unsigned long long uv1 = *(const unsigned long long*)&wdup2[k][2 * (lane + 32)];
                unsigned long long uv2 = *(const unsigned long long*)&wdup2[k][2 * (lane + 64)];
                unsigned long long uv3 = *(const unsigned long long*)&wdup2[k][2 * (lane + 96)];
                fma2(acc[0][0], bA.x, uv0); fma2(acc[0][1], bA.x, uv1);
                fma2(acc[0][2], bA.x, uv2); fma2(acc[0][3], bA.x, uv3);
                fma2(acc[1][0], bA.y, uv0); fma2(acc[1][1], bA.y, uv1);
                fma2(acc[1][2], bA.y, uv2); fma2(acc[1][3], bA.y, uv3);
                fma2(acc[2][0], bB.x, uv0); fma2(acc[2][1], bB.x, uv1);
                fma2(acc[2][2], bB.x, uv2); fma2(acc[2][3], bB.x, uv3);
                fma2(acc[3][0], bB.y, uv0); fma2(acc[3][1], bB.y, uv1);
                fma2(acc[3][2], bB.y, uv2); fma2(acc[3][3], bB.y, uv3);
            }
        }
    }

    // epilogue: store + optional fused BN column stats
    float cs[4] = {0.f, 0.f, 0.f, 0.f};
    float cq[4] = {0.f, 0.f, 0.f, 0.f};
#pragma unroll
    for (int rp = 0; rp < 4; rp++) {
        int r_lo = row0 + w * 8 + 2 * rp;
        int r_hi = r_lo + 1;
#pragma unroll
        for (int j = 0; j < 4; j++) {
            float2 v = upk2(acc[rp][j]);
            int c = lane + 32 * j;
            if (r_lo < n) {
                C[(size_t)r_lo * HID + c] = v.x;
                if (STATS >= 0) { cs[j] += v.x; cq[j] += v.x * v.x; }
            }
            if (r_hi < n) {
                C[(size_t)r_hi * HID + c] = v.y;
                if (STATS >= 0) { cs[j] += v.y; cq[j] += v.y * v.y; }
            }
        }
    }
    if (STATS >= 0) {
#pragma unroll
        for (int j = 0; j < 4; j++) {
            atomicAdd(&ssum[lane + 32 * j], cs[j]);
            atomicAdd(&ssq[lane + 32 * j], cq[j]);
        }
        __syncthreads();
        if (tid < HID) {
            atomicAdd(&g_sum[STATS * HID + tid], ssum[tid]);
            atomicAdd(&g_sumsq[STATS * HID + tid], ssq[tid]);
        }
    }
}

// ---------------- BN finalize + apply ----------------
__global__ void stats_final_kernel(const float* __restrict__ gamma, const float* __restrict__ beta,
                                   float inv_n, int slot) {
    int c = threadIdx.x;
    float mu = g_sum[slot * HID + c] * inv_n;
    float var = g_sumsq[slot * HID + c] * inv_n - mu * mu;
    float sc = gamma[c] * rsqrtf(var + BN_EPS);
    g_scale[c] = sc;
    g_shift[c] = beta[c] - mu * sc;
}

// ACT: 0 = relu, 1 = sigmoid
template<int ACT>
__global__ void bn_act_kernel(float* __restrict__ h, int n) {
    size_t i = (size_t)blockIdx.x * blockDim.x + threadIdx.x;
    size_t total = (size_t)n * (HID / 4);
    if (i >= total) return;
    int c = (int)(i & 31) * 4;
    float4 v = ((float4*)h)[i];
    float4 sc = *(float4*)&g_scale[c];
    float4 sh = *(float4*)&g_shift[c];
    v.x = v.x * sc.x + sh.x; v.y = v.y * sc.y + sh.y;
    v.z = v.z * sc.z + sh.z; v.w = v.w * sc.w + sh.w;
    if (ACT == 0) {
        v.x = fmaxf(v.x, 0.f); v.y = fmaxf(v.y, 0.f);
        v.z = fmaxf(v.z, 0.f); v.w = fmaxf(v.w, 0.f);
    } else {
        v.x = 1.f / (1.f + expf(-v.x)); v.y = 1.f / (1.f + expf(-v.y));
        v.z = 1.f / (1.f + expf(-v.z)); v.w = 1.f / (1.f + expf(-v.w));
    }
    ((float4*)h)[i] = v;
}

// ---------------- classifier + log_softmax ----------------
__global__ __launch_bounds__(256) void classifier_kernel(
    const float* __restrict__ hg, const float* __restrict__ hp,
    const float* __restrict__ Wc, const float* __restrict__ bc,
    float* __restrict__ out, int n)
{
    __shared__ float wcs[40 * 256];
    __shared__ float bcs[40];
    int tid = threadIdx.x;
    for (int i = tid; i < 40 * 256; i += 256) wcs[i] = Wc[i];
    if (tid < 40) bcs[tid] = bc[tid];
    __syncthreads();
    int r = blockIdx.x * 256 + tid;
    if (r >= n) return;

    float acc[40];
#pragma unroll
    for (int o = 0; o < 40; o++) acc[o] = bcs[o];

    for (int half = 0; half < 2; half++) {
        const float* src = half ? hp : hg;
        for (int k4 = 0; k4 < 32; k4++) {
            float4 z = *(const float4*)(src + (size_t)r * HID + k4 * 4);
            z.x = fmaxf(z.x, 0.f); z.y = fmaxf(z.y, 0.f);
            z.z = fmaxf(z.z, 0.f); z.w = fmaxf(z.w, 0.f);
            int kb = half * 128 + k4 * 4;
#pragma unroll
            for (int o = 0; o < 40; o++) {
                float4 wv = *(float4*)&wcs[o * 256 + kb];
                acc[o] += z.x * wv.x + z.y * wv.y + z.z * wv.z + z.w * wv.w;
            }
        }
    }
    float m = acc[0];
#pragma unroll
    for (int o = 1; o < 40; o++) m = fmaxf(m, acc[o]);
    float s = 0.f;
#pragma unroll
    for (int o = 0; o < 40; o++) s += expf(acc[o] - m);
    float lse = m + logf(s);
    float* op = out + (size_t)r * 40;
#pragma unroll
    for (int o = 0; o < 40; o++) op[o] = acc[o] - lse;
}

// ---------------- launcher ----------------
extern "C" void kernel_launch(void* const* d_in, const int* in_sizes, int n_in,
                              void* d_out, int out_size) {
    const float* x           = (const float*)d_in[0];
    const float* alpha       = (const float*)d_in[1];
    const int*   ei          = (const int*)d_in[2];
    const float* sage_Wl     = (const float*)d_in[3];
    const float* sage_bl     = (const float*)d_in[4];
    const float* sage_Wr     = (const float*)d_in[5];
    const float* sage_bng    = (const float*)d_in[6];
    const float* sage_bnb    = (const float*)d_in[7];
    const float* mlp_W0      = (const float*)d_in[8];
    const float* mlp_b0      = (const float*)d_in[9];
    const float* mlp_W1      = (const float*)d_in[10];
    const float* mlp_b1      = (const float*)d_in[11];
    const float* mlp_W2      = (const float*)d_in[12];
    const float* mlp_b2      = (const float*)d_in[13];
    const float* mlp_bng     = (const float*)d_in[14];
    const float* mlp_bnb     = (const float*)d_in[15];
    const float* W_cls       = (const float*)d_in[16];
    const float* b_cls       = (const float*)d_in[17];
    const float* temperature = (const float*)d_in[18];

    int n = in_sizes[0] / HID;
    int E = in_sizes[2] / 2;
    const int* src = ei;
    const int* tgt = ei + E;
    float* out = (float*)d_out;

    float *h1, *h2, *agg, *p, *p2;
    cudaGetSymbolAddress((void**)&h1,  g_h1);
    cudaGetSymbolAddress((void**)&h2,  g_h2);
    cudaGetSymbolAddress((void**)&agg, g_agg);
    cudaGetSymbolAddress((void**)&p,   g_p);
    cudaGetSymbolAddress((void**)&p2,  g_p2);

    const int TB = 256;
    int nodeBlocks = (n + TB - 1) / TB;
    int gemmBlocks = (n + 63) / 64;
    float inv_n = 1.0f / (float)n;
    size_t aggBytes = (size_t)n * HID * sizeof(float);
    long long scatThreads = (long long)E * 32;
    int scatBlocks = (int)((scatThreads + TB - 1) / TB);
    long long simThreads = (long long)E * 8;
    int simBlocks = (int)((simThreads + TB - 1) / TB);
    int bnBlocks = (int)(((size_t)n * (HID / 4) + TB - 1) / TB);

    // ---- SAGE chain first (so ncu -s window lands on scatter/gemm) ----
    init_kernel<<<nodeBlocks, TB>>>(n);
    count_kernel<<<(E + TB - 1) / TB, TB>>>(tgt, E);
    cudaMemsetAsync(agg, 0, aggBytes);
    scatter_kernel<<<scatBlocks, TB>>>(x, src, tgt, E);
    gemm_kernel<128, true, true, 0><<<gemmBlocks, TB>>>(agg, x, sage_Wl, sage_Wr, sage_bl, h1, n);
    stats_final_kernel<<<1, HID>>>(sage_bng, sage_bnb, inv_n, 0);
    bn_act_kernel<0><<<bnBlocks, TB>>>(h1, n);

    cudaMemsetAsync(agg, 0, aggBytes);
    scatter_kernel<<<scatBlocks, TB>>>(h1, src, tgt, E);
    gemm_kernel<128, true, true, 1><<<gemmBlocks, TB>>>(agg, h1, sage_Wl + 16384, sage_Wr + 16384,
                                                        sage_bl + HID, h2, n);
    stats_final_kernel<<<1, HID>>>(sage_bng + HID, sage_bnb + HID, inv_n, 1);
    bn_act_kernel<0><<<bnBlocks, TB>>>(h2, n);

    cudaMemsetAsync(agg, 0, aggBytes);
    scatter_kernel<<<scatBlocks, TB>>>(h2, src, tgt, E);
    gemm_kernel<128, true, true, -1><<<gemmBlocks, TB>>>(agg, h2, sage_Wl + 32768, sage_Wr + 32768,
                                                         sage_bl + 2 * HID, h1, n);

    // ---- Proto MLP branch ----
    gemm_kernel<64, false, false, 2><<<gemmBlocks, TB>>>(alpha, nullptr, mlp_W0, nullptr, mlp_b0, p, n);
    stats_final_kernel<<<1, HID>>>(mlp_bng, mlp_bnb, inv_n, 2);
    bn_act_kernel<1><<<bnBlocks, TB>>>(p, n);

    gemm_kernel<128, false, false, 3><<<gemmBlocks, TB>>>(p, nullptr, mlp_W1, nullptr, mlp_b1, p2, n);
    stats_final_kernel<<<1, HID>>>(mlp_bng + HID, mlp_bnb + HID, inv_n, 3);
    bn_act_kernel<1><<<bnBlocks, TB>>>(p2, n);

    gemm_kernel<128, false, false, -1><<<gemmBlocks, TB>>>(p2, nullptr, mlp_W2, nullptr, mlp_b2, p, n);

    // ---- fusion + classifier + log_softmax ----
    classifier_kernel<<<nodeBlocks, TB>>>(h1, p, W_cls, b_cls, out, n);

    // ---- gate branch (independent; moved last) ----
    normalize_alpha_kernel<<<nodeBlocks, TB>>>(alpha, n);
    edge_sim_kernel<<<simBlocks, TB>>>(src, tgt, E);
    gate_final_kernel<<<nodeBlocks, TB>>>(temperature, out + (size_t)n * 40, n);
}

// round 5
// speedup vs baseline: 2.0755x; 2.0755x over previous
#include <cuda_runtime.h>
#include <cuda_bf16.h>
#include <math.h>

#define NMAX 100000
#define EMAX 1700000
#define HID 128
#define PROTO 64
#define BN_EPS 1e-5f

// ---------------- scratch (device globals: no allocation allowed) ----------------
__device__ float g_h1[NMAX * HID];
__device__ float g_h2[NMAX * HID];
__device__ float g_agg[NMAX * HID];
__device__ float g_p[NMAX * HID];
__device__ float g_p2[NMAX * HID];
__device__ float g_an[NMAX * PROTO];
__device__ int   g_cnt[NMAX];
__device__ int   g_off[NMAX + 1];
__device__ int   g_cur[NMAX];
__device__ int   g_csr[EMAX];
__device__ float g_sum[4 * HID];
__device__ float g_sumsq[4 * HID];
__device__ float g_scale[HID];
__device__ float g_shift[HID];

// ---------------- init (stats only) ----------------
__global__ void init_kernel() {
    int v = blockIdx.x * blockDim.x + threadIdx.x;
    if (v < 4 * HID) { g_sum[v] = 0.f; g_sumsq[v] = 0.f; }
}

__global__ void count_kernel(const int* __restrict__ tgt, int E, int n) {
    int e = blockIdx.x * blockDim.x + threadIdx.x;
    if (e < n && e < NMAX) g_cnt[e] = 0;          // also zero counters (grid covers max(E,n))
}
__global__ void count2_kernel(const int* __restrict__ tgt, int E) {
    int e = blockIdx.x * blockDim.x + threadIdx.x;
    if (e < E) atomicAdd(&g_cnt[tgt[e]], 1);
}

// ---------------- exclusive scan over g_cnt -> g_off, g_cur (single block) ----------------
__global__ void scan_kernel(int n) {
    __shared__ int wsum[32];
    __shared__ int carry_s;
    int tid = threadIdx.x, lane = tid & 31, wid = tid >> 5;
    if (tid == 0) carry_s = 0;
    __syncthreads();
    for (int base = 0; base < n; base += 1024) {
        int i = base + tid;
        int v = (i < n) ? g_cnt[i] : 0;
        int s = v;
#pragma unroll
        for (int d = 1; d < 32; d <<= 1) {
            int t = __shfl_up_sync(0xFFFFFFFFu, s, d);
            if (lane >= d) s += t;
        }
        if (lane == 31) wsum[wid] = s;
        __syncthreads();
        if (wid == 0) {
            int ws = wsum[lane];
            int e = ws;
#pragma unroll
            for (int d = 1; d < 32; d <<= 1) {
                int t = __shfl_up_sync(0xFFFFFFFFu, e, d);
                if (lane >= d) e += t;
            }
            wsum[lane] = e - ws;  // exclusive
        }
        __syncthreads();
        int excl = carry_s + wsum[wid] + s - v;
        if (i < n) { g_off[i] = excl; g_cur[i] = excl; }
        __syncthreads();
        if (tid == 1023) carry_s = excl + v;   // chunk total folded in
        __syncthreads();
    }
    if (tid == 0) g_off[n] = carry_s;
}

__global__ void fill_kernel(const int* __restrict__ src, const int* __restrict__ tgt, int E) {
    int e = blockIdx.x * blockDim.x + threadIdx.x;
    if (e >= E) return;
    int t = tgt[e];
    int pos = atomicAdd(&g_cur[t], 1);
    g_csr[pos] = src[e];
}

// ---------------- gather aggregation (segment mean), warp per node ----------------
__global__ __launch_bounds__(256) void gather_agg_kernel(const float* __restrict__ h,
                                                         float* __restrict__ agg, int n) {
    int lane = threadIdx.x & 31;
    int v = blockIdx.x * 8 + (threadIdx.x >> 5);
    if (v >= n) return;
    int d0 = g_off[v], d1 = g_off[v + 1];
    float4 acc = make_float4(0.f, 0.f, 0.f, 0.f);
    for (int j0 = d0; j0 < d1; j0 += 32) {
        int m = d1 - j0; if (m > 32) m = 32;
        int ul = (j0 + lane < d1) ? g_csr[j0 + lane] : 0;
        for (int t = 0; t < m; t++) {
            int u = __shfl_sync(0xFFFFFFFFu, ul, t);
            float4 x = *(const float4*)(h + (size_t)u * HID + lane * 4);
            acc.x += x.x; acc.y += x.y; acc.z += x.z; acc.w += x.w;
        }
    }
    int c = d1 - d0;
    float inv = 1.0f / (float)(c > 0 ? c : 1);
    acc.x *= inv; acc.y *= inv; acc.z *= inv; acc.w *= inv;
    *(float4*)(agg + (size_t)v * HID + lane * 4) = acc;
}

// ---------------- gate branch ----------------
__global__ void normalize_alpha_kernel(const float* __restrict__ alpha, int n) {
    int v = blockIdx.x * blockDim.x + threadIdx.x;
    if (v >= n) return;
    const float4* a = (const float4*)(alpha + (size_t)v * PROTO);
    float4 vals[16];
    float ss = 0.f;
#pragma unroll
    for (int i = 0; i < 16; i++) {
        vals[i] = a[i];
        ss += vals[i].x * vals[i].x + vals[i].y * vals[i].y +
              vals[i].z * vals[i].z + vals[i].w * vals[i].w;
    }
    float inv = 1.0f / fmaxf(sqrtf(ss), 1e-12f);
    float4* o = (float4*)(g_an + (size_t)v * PROTO);
#pragma unroll
    for (int i = 0; i < 16; i++) {
        float4 t = vals[i];
        t.x *= inv; t.y *= inv; t.z *= inv; t.w *= inv;
        o[i] = t;
    }
}

// warp per node: sim_sum = 1 (self) + dot(an[v], sum_{u in N(v)} an[u])
__global__ __launch_bounds__(256) void gate_gather_kernel(const float* __restrict__ temp,
                                                          float* __restrict__ out, int n) {
    int lane = threadIdx.x & 31;
    int v = blockIdx.x * 8 + (threadIdx.x >> 5);
    if (v >= n) return;
    int d0 = g_off[v], d1 = g_off[v + 1];
    float2 acc = make_float2(0.f, 0.f);
    for (int j0 = d0; j0 < d1; j0 += 32) {
        int m = d1 - j0; if (m > 32) m = 32;
        int ul = (j0 + lane < d1) ? g_csr[j0 + lane] : 0;
        for (int t = 0; t < m; t++) {
            int u = __shfl_sync(0xFFFFFFFFu, ul, t);
            float2 x = *(const float2*)(g_an + (size_t)u * PROTO + lane * 2);
            acc.x += x.x; acc.y += x.y;
        }
    }
    float2 av = *(const float2*)(g_an + (size_t)v * PROTO + lane * 2);
    float d = acc.x * av.x + acc.y * av.y;
#pragma unroll
    for (int s = 16; s > 0; s >>= 1) d += __shfl_down_sync(0xFFFFFFFFu, d, s);
    if (lane == 0) {
        float tv = __ldg(temp);
        float m = (1.0f + d) / (float)((d1 - d0) + 1);
        out[v] = 1.0f / (1.0f + expf(-tv * m));
    }
}

// ---------------- GEMM (R1 structure, plain FFMA) + fused BN column stats ----------------
// C[r][c] = bias[c] + sum_k A1[r][k]*W1[c][k] (+ A2[r][k]*W2[c][k])
// tile 64 rows x 128 cols, 256 threads, each thread 8 rows x 4 cols
template<int K, bool DUAL, int STATS>
__global__ __launch_bounds__(256) void gemm_kernel(
    const float* __restrict__ A1, const float* __restrict__ A2,
    const float* __restrict__ W1, const float* __restrict__ W2,
    const float* __restrict__ bias, float* __restrict__ C, int n)
{
    constexpr int BM = 64, KC = 16;
    __shared__ __align__(16) float as1[BM][KC];
    __shared__ __align__(16) float as2[BM][KC];
    __shared__ __align__(16) float wt1[KC][HID];
    __shared__ __align__(16) float wt2[KC][HID];
    __shared__ float ssum[HID], ssq[HID];

    const int tid  = threadIdx.x;
    const int lane = tid & 31;
    const int w    = tid >> 5;
    const int row0 = blockIdx.x * BM;

    if (STATS >= 0 && tid < HID) { ssum[tid] = 0.f; ssq[tid] = 0.f; }

    float4 b4 = *(const float4*)(bias + lane * 4);
    float acc[8][4];
#pragma unroll
    for (int r = 0; r < 8; r++) { acc[r][0] = b4.x; acc[r][1] = b4.y; acc[r][2] = b4.z; acc[r][3] = b4.w; }

    for (int k0 = 0; k0 < K; k0 += KC) {
        __syncthreads();
        for (int i = tid; i < BM * KC / 4; i += 256) {
            int r  = i / (KC / 4);
            int c4 = (i % (KC / 4)) * 4;
            int gr = row0 + r;
            float4 v = make_float4(0.f, 0.f, 0.f, 0.f);
            if (gr < n) v = *(const float4*)(A1 + (size_t)gr * K + k0 + c4);
            *(float4*)&as1[r][c4] = v;
            if (DUAL) {
                float4 u = make_float4(0.f, 0.f, 0.f, 0.f);
                if (gr < n) u = *(const float4*)(A2 + (size_t)gr * K + k0 + c4);
                *(float4*)&as2[r][c4] = u;
            }
        }
        {
            int c  = tid & 127;
            int kh = (tid >> 7) * (KC / 2);
#pragma unroll
            for (int j = 0; j < KC / 2; j += 4) {
                float4 v = *(const float4*)(W1 + (size_t)c * K + k0 + kh + j);
                wt1[kh + j + 0][c] = v.x; wt1[kh + j + 1][c] = v.y;
                wt1[kh + j + 2][c] = v.z; wt1[kh + j + 3][c] = v.w;
                if (DUAL) {
                    float4 u = *(const float4*)(W2 + (size_t)c * K + k0 + kh + j);
                    wt2[kh + j + 0][c] = u.x; wt2[kh + j + 1][c] = u.y;
                    wt2[kh + j + 2][c] = u.z; wt2[kh + j + 3][c] = u.w;
                }
            }
        }
        __syncthreads();
#pragma unroll
        for (int kk = 0; kk < KC; kk += 4) {
            float4 a1v[8], a2v[8];
#pragma unroll
            for (int r = 0; r < 8; r++) a1v[r] = *(float4*)&as1[w * 8 + r][kk];
            if (DUAL) {
#pragma unroll
                for (int r = 0; r < 8; r++) a2v[r] = *(float4*)&as2[w * 8 + r][kk];
            }
#pragma unroll
            for (int q = 0; q < 4; q++) {
                float4 wv = *(float4*)&wt1[kk + q][lane * 4];
#pragma unroll
                for (int r = 0; r < 8; r++) {
                    float a = (q == 0) ? a1v[r].x : (q == 1) ? a1v[r].y : (q == 2) ? a1v[r].z : a1v[r].w;
                    acc[r][0] += a * wv.x; acc[r][1] += a * wv.y;
                    acc[r][2] += a * wv.z; acc[r][3] += a * wv.w;
                }
                if (DUAL) {
                    float4 w2v = *(float4*)&wt2[kk + q][lane * 4];
#pragma unroll
                    for (int r = 0; r < 8; r++) {
                        float a = (q == 0) ? a2v[r].x : (q == 1) ? a2v[r].y : (q == 2) ? a2v[r].z : a2v[r].w;
                        acc[r][0] += a * w2v.x; acc[r][1] += a * w2v.y;
                        acc[r][2] += a * w2v.z; acc[r][3] += a * w2v.w;
                    }
                }
            }
        }
    }

    float cs0 = 0.f, cs1 = 0.f, cs2 = 0.f, cs3 = 0.f;
    float cq0 = 0.f, cq1 = 0.f, cq2 = 0.f, cq3 = 0.f;
#pragma unroll
    for (int r = 0; r < 8; r++) {
        int gr = row0 + w * 8 + r;
        if (gr < n) {
            float4 o = make_float4(acc[r][0], acc[r][1], acc[r][2], acc[r][3]);
            *(float4*)(C + (size_t)gr * HID + lane * 4) = o;
            if (STATS >= 0) {
                cs0 += o.x; cs1 += o.y; cs2 += o.z; cs3 += o.w;
                cq0 += o.x * o.x; cq1 += o.y * o.y; cq2 += o.z * o.z; cq3 += o.w * o.w;
            }
        }
    }
    if (STATS >= 0) {
        atomicAdd(&ssum[lane * 4 + 0], cs0); atomicAdd(&ssum[lane * 4 + 1], cs1);
        atomicAdd(&ssum[lane * 4 + 2], cs2); atomicAdd(&ssum[lane * 4 + 3], cs3);
        atomicAdd(&ssq[lane * 4 + 0], cq0);  atomicAdd(&ssq[lane * 4 + 1], cq1);
        atomicAdd(&ssq[lane * 4 + 2], cq2);  atomicAdd(&ssq[lane * 4 + 3], cq3);
        __syncthreads();
        if (tid < HID) {
            atomicAdd(&g_sum[STATS * HID + tid], ssum[tid]);
            atomicAdd(&g_sumsq[STATS * HID + tid], ssq[tid]);
        }
    }
}

// ---------------- BN finalize + apply ----------------
__global__ void stats_final_kernel(const float* __restrict__ gamma, const float* __restrict__ beta,
                                   float inv_n, int slot) {
    int c = threadIdx.x;
    float mu = g_sum[slot * HID + c] * inv_n;
    float var = g_sumsq[slot * HID + c] * inv_n - mu * mu;
    float sc = gamma[c] * rsqrtf(var + BN_EPS);
    g_scale[c] = sc;
    g_shift[c] = beta[c] - mu * sc;
}

// ACT: 0 = relu, 1 = sigmoid
template<int ACT>
__global__ void bn_act_kernel(float* __restrict__ h, int n) {
    size_t i = (size_t)blockIdx.x * blockDim.x + threadIdx.x;
    size_t total = (size_t)n * (HID / 4);
    if (i >= total) return;
    int c = (int)(i & 31) * 4;
    float4 v = ((float4*)h)[i];
    float4 sc = *(float4*)&g_scale[c];
    float4 sh = *(float4*)&g_shift[c];
    v.x = v.x * sc.x + sh.x; v.y = v.y * sc.y + sh.y;
    v.z = v.z * sc.z + sh.z; v.w = v.w * sc.w + sh.w;
    if (ACT == 0) {
        v.x = fmaxf(v.x, 0.f); v.y = fmaxf(v.y, 0.f);
        v.z = fmaxf(v.z, 0.f); v.w = fmaxf(v.w, 0.f);
    } else {
        v.x = 1.f / (1.f + expf(-v.x)); v.y = 1.f / (1.f + expf(-v.y));
        v.z = 1.f / (1.f + expf(-v.z)); v.w = 1.f / (1.f + expf(-v.w));
    }
    ((float4*)h)[i] = v;
}

// ---------------- classifier + log_softmax ----------------
__global__ __launch_bounds__(256) void classifier_kernel(
    const float* __restrict__ hg, const float* __restrict__ hp,
    const float* __restrict__ Wc, const float* __restrict__ bc,
    float* __restrict__ out, int n)
{
    __shared__ float wcs[40 * 256];
    __shared__ float bcs[40];
    int tid = threadIdx.x;
    for (int i = tid; i < 40 * 256; i += 256) wcs[i] = Wc[i];
    if (tid < 40) bcs[tid] = bc[tid];
    __syncthreads();
    int r = blockIdx.x * 256 + tid;
    if (r >= n) return;

    float acc[40];
#pragma unroll
    for (int o = 0; o < 40; o++) acc[o] = bcs[o];

    for (int half = 0; half < 2; half++) {
        const float* src = half ? hp : hg;
        for (int k4 = 0; k4 < 32; k4++) {
            float4 z = *(const float4*)(src + (size_t)r * HID + k4 * 4);
            z.x = fmaxf(z.x, 0.f); z.y = fmaxf(z.y, 0.f);
            z.z = fmaxf(z.z, 0.f); z.w = fmaxf(z.w, 0.f);
            int kb = half * 128 + k4 * 4;
#pragma unroll
            for (int o = 0; o < 40; o++) {
                float4 wv = *(float4*)&wcs[o * 256 + kb];
                acc[o] += z.x * wv.x + z.y * wv.y + z.z * wv.z + z.w * wv.w;
            }
        }
    }
    float m = acc[0];
#pragma unroll
    for (int o = 1; o < 40; o++) m = fmaxf(m, acc[o]);
    float s = 0.f;
#pragma unroll
    for (int o = 0; o < 40; o++) s += expf(acc[o] - m);
    float lse = m + logf(s);
    float* op = out + (size_t)r * 40;
#pragma unroll
    for (int o = 0; o < 40; o++) op[o] = acc[o] - lse;
}

// ---------------- launcher ----------------
extern "C" void kernel_launch(void* const* d_in, const int* in_sizes, int n_in,
                              void* d_out, int out_size) {
    const float* x           = (const float*)d_in[0];
    const float* alpha       = (const float*)d_in[1];
    const int*   ei          = (const int*)d_in[2];
    const float* sage_Wl     = (const float*)d_in[3];
    const float* sage_bl     = (const float*)d_in[4];
    const float* sage_Wr     = (const float*)d_in[5];
    const float* sage_bng    = (const float*)d_in[6];
    const float* sage_bnb    = (const float*)d_in[7];
    const float* mlp_W0      = (const float*)d_in[8];
    const float* mlp_b0      = (const float*)d_in[9];
    const float* mlp_W1      = (const float*)d_in[10];
    const float* mlp_b1      = (const float*)d_in[11];
    const float* mlp_W2      = (const float*)d_in[12];
    const float* mlp_b2      = (const float*)d_in[13];
    const float* mlp_bng     = (const float*)d_in[14];
    const float* mlp_bnb     = (const float*)d_in[15];
    const float* W_cls       = (const float*)d_in[16];
    const float* b_cls       = (const float*)d_in[17];
    const float* temperature = (const float*)d_in[18];

    int n = in_sizes[0] / HID;
    int E = in_sizes[2] / 2;
    const int* src = ei;
    const int* tgt = ei + E;
    float* out = (float*)d_out;

    float *h1, *h2, *agg, *p, *p2;
    cudaGetSymbolAddress((void**)&h1,  g_h1);
    cudaGetSymbolAddress((void**)&h2,  g_h2);
    cudaGetSymbolAddress((void**)&agg, g_agg);
    cudaGetSymbolAddress((void**)&p,   g_p);
    cudaGetSymbolAddress((void**)&p2,  g_p2);

    const int TB = 256;
    int nodeBlocks = (n + TB - 1) / TB;
    int warpNodeBlocks = (n + 7) / 8;
    int gemmBlocks = (n + 63) / 64;
    float inv_n = 1.0f / (float)n;
    int bnBlocks = (int)(((size_t)n * (HID / 4) + TB - 1) / TB);
    int eBlocks = (E + TB - 1) / TB;
    int cntBlocks = ((n > E ? n : E) + TB - 1) / TB;

    // ---- CSR build + init ----
    init_kernel<<<2, TB>>>();
    count_kernel<<<cntBlocks, TB>>>(tgt, E, n);
    count2_kernel<<<eBlocks, TB>>>(tgt, E);
    scan_kernel<<<1, 1024>>>(n);
    fill_kernel<<<eBlocks, TB>>>(src, tgt, E);
    normalize_alpha_kernel<<<nodeBlocks, TB>>>(alpha, n);

    // ---- SAGE layer 0 ----
    gather_agg_kernel<<<warpNodeBlocks, TB>>>(x, agg, n);
    gemm_kernel<128, true, 0><<<gemmBlocks, TB>>>(agg, x, sage_Wl, sage_Wr, sage_bl, h1, n);
    stats_final_kernel<<<1, HID>>>(sage_bng, sage_bnb, inv_n, 0);
    bn_act_kernel<0><<<bnBlocks, TB>>>(h1, n);

    // ---- SAGE layer 1 ----
    gather_agg_kernel<<<warpNodeBlocks, TB>>>(h1, agg, n);
    gemm_kernel<128, true, 1><<<gemmBlocks, TB>>>(agg, h1, sage_Wl + 16384, sage_Wr + 16384,
                                                  sage_bl + HID, h2, n);
    stats_final_kernel<<<1, HID>>>(sage_bng + HID, sage_bnb + HID, inv_n, 1);
    bn_act_kernel<0><<<bnBlocks, TB>>>(h2, n);

    // ---- SAGE layer 2 (no BN/act) ----
    gather_agg_kernel<<<warpNodeBlocks, TB>>>(h2, agg, n);
    gemm_kernel<128, true, -1><<<gemmBlocks, TB>>>(agg, h2, sage_Wl + 32768, sage_Wr + 32768,
                                                   sage_bl + 2 * HID, h1, n);

    // ---- Proto MLP branch ----
    gemm_kernel<64, false, 2><<<gemmBlocks, TB>>>(alpha, nullptr, mlp_W0, nullptr, mlp_b0, p, n);
    stats_final_kernel<<<1, HID>>>(mlp_bng, mlp_bnb, inv_n, 2);
    bn_act_kernel<1><<<bnBlocks, TB>>>(p, n);

    gemm_kernel<128, false, 3><<<gemmBlocks, TB>>>(p, nullptr, mlp_W1, nullptr, mlp_b1, p2, n);
    stats_final_kernel<<<1, HID>>>(mlp_bng + HID, mlp_bnb + HID, inv_n, 3);
    bn_act_kernel<1><<<bnBlocks, TB>>>(p2, n);

    gemm_kernel<128, false, -1><<<gemmBlocks, TB>>>(p2, nullptr, mlp_W2, nullptr, mlp_b2, p, n);

    // ---- fusion + classifier + log_softmax ----
    classifier_kernel<<<nodeBlocks, TB>>>(h1, p, W_cls, b_cls, out, n);

    // ---- gate (gather form) ----
    gate_gather_kernel<<<warpNodeBlocks, TB>>>(temperature, out + (size_t)n * 40, n);
}